// round 2
// baseline (speedup 1.0000x reference)
#include <cuda_runtime.h>
#include <math.h>

#define NN 50000
#define NE 800000
#define ET (NE + NN)
#define FIN 128
#define D1 128      // H*C = 4*32
#define H1 4
#define CH 32

// ---------------- scratch (device globals; no allocation allowed) -------------
__device__ float    g_h1  [NN * D1];
__device__ float    g_es1 [NN * H1];
__device__ float    g_ed1 [NN * H1];
__device__ unsigned g_m1  [NN * H1];
__device__ float    g_den1[NN * H1];
__device__ float    g_e1  [ET * H1];
__device__ float    g_out1[NN * D1];
__device__ float    g_h2  [NN * CH];
__device__ float    g_es2 [NN];
__device__ float    g_ed2 [NN];
__device__ unsigned g_m2  [NN];
__device__ float    g_den2[NN];
__device__ float    g_e2  [ET];
__device__ float    g_out2[NN * CH];

// order-preserving float<->uint for atomicMax on floats
__device__ __forceinline__ unsigned fenc(float f) {
    unsigned u = __float_as_uint(f);
    return (u & 0x80000000u) ? ~u : (u | 0x80000000u);
}
__device__ __forceinline__ float fdec(unsigned u) {
    return __uint_as_float((u & 0x80000000u) ? (u & 0x7FFFFFFFu) : ~u);
}
__device__ __forceinline__ float lrelu(float x) { return x > 0.f ? x : 0.2f * x; }

// ---------------- init: zero accumulators --------------------------------------
__global__ void k_init() {
    int i = blockIdx.x * blockDim.x + threadIdx.x;
    int stride = gridDim.x * blockDim.x;
    for (int j = i; j < NN * D1; j += stride) {
        g_out1[j] = 0.f;
        if (j < NN * H1) { g_m1[j] = 0u; g_den1[j] = 0.f; }
        if (j < NN * CH) g_out2[j] = 0.f;
        if (j < NN)      { g_m2[j] = 0u; g_den2[j] = 0.f; }
    }
}

// ---------------- layer1 GEMM + attention logits -------------------------------
// 16 nodes per block, 128 threads. Each thread owns one output column.
__global__ void k_gemm1(const float* __restrict__ x, const float* __restrict__ W1,
                        const float* __restrict__ as1, const float* __restrict__ ad1) {
    __shared__ float xs[16][FIN];
    const int t = threadIdx.x;
    const int nb = blockIdx.x * 16;
#pragma unroll
    for (int r = 0; r < 16; r++) xs[r][t] = x[(nb + r) * FIN + t];
    __syncthreads();

    float acc[16];
#pragma unroll
    for (int r = 0; r < 16; r++) acc[r] = 0.f;

    for (int k = 0; k < FIN; k++) {
        float w = W1[k * D1 + t];
#pragma unroll
        for (int r = 0; r < 16; r++) acc[r] += xs[r][k] * w;
    }

    const float a_s = as1[t], a_d = ad1[t];
    const int lane = t & 31, head = t >> 5;
#pragma unroll
    for (int r = 0; r < 16; r++) {
        int n = nb + r;
        g_h1[n * D1 + t] = acc[r];
        float s = acc[r] * a_s;
        float d = acc[r] * a_d;
#pragma unroll
        for (int o = 16; o; o >>= 1) {
            s += __shfl_xor_sync(0xFFFFFFFFu, s, o);
            d += __shfl_xor_sync(0xFFFFFFFFu, d, o);
        }
        if (lane == 0) { g_es1[n * H1 + head] = s; g_ed1[n * H1 + head] = d; }
    }
}

// ---------------- layer1 edge passes -------------------------------------------
__device__ __forceinline__ void edge_sd(const int* __restrict__ ei, int i, int& s, int& d) {
    if (i < NE) { s = ei[i]; d = ei[NE + i]; } else { s = d = i - NE; }
}

__global__ void k_edgeA1(const int* __restrict__ ei) {
    int i = blockIdx.x * blockDim.x + threadIdx.x;
    if (i >= ET) return;
    int s, d; edge_sd(ei, i, s, d);
    float4 es = *(const float4*)(g_es1 + s * 4);
    float4 ed = *(const float4*)(g_ed1 + d * 4);
    float4 e;
    e.x = lrelu(es.x + ed.x); e.y = lrelu(es.y + ed.y);
    e.z = lrelu(es.z + ed.z); e.w = lrelu(es.w + ed.w);
    *(float4*)(g_e1 + (size_t)i * 4) = e;
    atomicMax(&g_m1[d * 4 + 0], fenc(e.x));
    atomicMax(&g_m1[d * 4 + 1], fenc(e.y));
    atomicMax(&g_m1[d * 4 + 2], fenc(e.z));
    atomicMax(&g_m1[d * 4 + 3], fenc(e.w));
}

__global__ void k_edgeB1(const int* __restrict__ ei) {
    int i = blockIdx.x * blockDim.x + threadIdx.x;
    if (i >= ET) return;
    int s, d; edge_sd(ei, i, s, d);
    float4 e = *(const float4*)(g_e1 + (size_t)i * 4);
    float4 ex;
    ex.x = expf(e.x - fdec(g_m1[d * 4 + 0]));
    ex.y = expf(e.y - fdec(g_m1[d * 4 + 1]));
    ex.z = expf(e.z - fdec(g_m1[d * 4 + 2]));
    ex.w = expf(e.w - fdec(g_m1[d * 4 + 3]));
    *(float4*)(g_e1 + (size_t)i * 4) = ex;
    atomicAdd(&g_den1[d * 4 + 0], ex.x);
    atomicAdd(&g_den1[d * 4 + 1], ex.y);
    atomicAdd(&g_den1[d * 4 + 2], ex.z);
    atomicAdd(&g_den1[d * 4 + 3], ex.w);
}

// one warp per edge; lane c covers channel c of each of 4 heads
__global__ void k_edgeC1(const int* __restrict__ ei) {
    int w = (blockIdx.x * blockDim.x + threadIdx.x) >> 5;
    int lane = threadIdx.x & 31;
    if (w >= ET) return;
    int s, d; edge_sd(ei, w, s, d);
    float a = 0.f;
    if (lane < 4) a = g_e1[(size_t)w * 4 + lane] / (g_den1[d * 4 + lane] + 1e-16f);
    float al0 = __shfl_sync(0xFFFFFFFFu, a, 0);
    float al1 = __shfl_sync(0xFFFFFFFFu, a, 1);
    float al2 = __shfl_sync(0xFFFFFFFFu, a, 2);
    float al3 = __shfl_sync(0xFFFFFFFFu, a, 3);
    const float* hs = g_h1 + (size_t)s * D1;
    float* od = g_out1 + (size_t)d * D1;
    atomicAdd(od + 0  + lane, hs[0  + lane] * al0);
    atomicAdd(od + 32 + lane, hs[32 + lane] * al1);
    atomicAdd(od + 64 + lane, hs[64 + lane] * al2);
    atomicAdd(od + 96 + lane, hs[96 + lane] * al3);
}

// ---------------- finalize layer1 (+b1, relu), GEMM2, attention logits ----------
__global__ void k_fin1_gemm2(const float* __restrict__ b1, const float* __restrict__ W2,
                             const float* __restrict__ as2, const float* __restrict__ ad2) {
    __shared__ float xs[16][D1];
    __shared__ float sh2[16][CH + 1];
    const int t = threadIdx.x;
    const int nb = blockIdx.x * 16;
    const float bt = b1[t];
#pragma unroll
    for (int r = 0; r < 16; r++)
        xs[r][t] = fmaxf(g_out1[(size_t)(nb + r) * D1 + t] + bt, 0.f);
    __syncthreads();

    const int c = t & 31, rg = t >> 5;
    float acc[4] = {0.f, 0.f, 0.f, 0.f};
    for (int k = 0; k < D1; k++) {
        float w = W2[k * CH + c];
        acc[0] += xs[rg     ][k] * w;
        acc[1] += xs[rg + 4 ][k] * w;
        acc[2] += xs[rg + 8 ][k] * w;
        acc[3] += xs[rg + 12][k] * w;
    }
#pragma unroll
    for (int i = 0; i < 4; i++) {
        int r = rg + 4 * i;
        g_h2[(size_t)(nb + r) * CH + c] = acc[i];
        sh2[r][c] = acc[i];
    }
    __syncthreads();

    const float as2c = as2[c], ad2c = ad2[c];
#pragma unroll
    for (int i = 0; i < 4; i++) {
        int r = rg + 4 * i;
        float s = sh2[r][c] * as2c;
        float d = sh2[r][c] * ad2c;
#pragma unroll
        for (int o = 16; o; o >>= 1) {
            s += __shfl_xor_sync(0xFFFFFFFFu, s, o);
            d += __shfl_xor_sync(0xFFFFFFFFu, d, o);
        }
        if (c == 0) { g_es2[nb + r] = s; g_ed2[nb + r] = d; }
    }
}

// ---------------- layer2 edge passes (1 head) -----------------------------------
__global__ void k_edgeA2(const int* __restrict__ ei) {
    int i = blockIdx.x * blockDim.x + threadIdx.x;
    if (i >= ET) return;
    int s, d; edge_sd(ei, i, s, d);
    float e = lrelu(g_es2[s] + g_ed2[d]);
    g_e2[i] = e;
    atomicMax(&g_m2[d], fenc(e));
}

__global__ void k_edgeB2(const int* __restrict__ ei) {
    int i = blockIdx.x * blockDim.x + threadIdx.x;
    if (i >= ET) return;
    int s, d; edge_sd(ei, i, s, d);
    float ex = expf(g_e2[i] - fdec(g_m2[d]));
    g_e2[i] = ex;
    atomicAdd(&g_den2[d], ex);
}

__global__ void k_edgeC2(const int* __restrict__ ei) {
    int w = (blockIdx.x * blockDim.x + threadIdx.x) >> 5;
    int lane = threadIdx.x & 31;
    if (w >= ET) return;
    int s, d; edge_sd(ei, w, s, d);
    float a = 0.f;
    if (lane == 0) a = g_e2[w] / (g_den2[d] + 1e-16f);
    a = __shfl_sync(0xFFFFFFFFu, a, 0);
    atomicAdd(&g_out2[(size_t)d * CH + lane], g_h2[(size_t)s * CH + lane] * a);
}

// ---------------- final: +b2, relu, FC, sigmoid ---------------------------------
__global__ void k_final(const float* __restrict__ b2, const float* __restrict__ fc_w,
                        const float* __restrict__ fc_b, float* __restrict__ out) {
    int n = (blockIdx.x * blockDim.x + threadIdx.x) >> 5;
    int lane = threadIdx.x & 31;
    if (n >= NN) return;
    float v = fmaxf(g_out2[(size_t)n * CH + lane] + b2[lane], 0.f);
    float p = v * fc_w[lane];
#pragma unroll
    for (int o = 16; o; o >>= 1) p += __shfl_xor_sync(0xFFFFFFFFu, p, o);
    if (lane == 0) out[n] = 1.f / (1.f + expf(-(p + fc_b[0])));
}

// ---------------- launch ---------------------------------------------------------
extern "C" void kernel_launch(void* const* d_in, const int* in_sizes, int n_in,
                              void* d_out, int out_size) {
    const float* x    = (const float*)d_in[0];
    const int*   ei   = (const int*)  d_in[1];
    const float* W1   = (const float*)d_in[2];
    const float* as1  = (const float*)d_in[3];
    const float* ad1  = (const float*)d_in[4];
    const float* b1   = (const float*)d_in[5];
    const float* W2   = (const float*)d_in[6];
    const float* as2  = (const float*)d_in[7];
    const float* ad2  = (const float*)d_in[8];
    const float* b2   = (const float*)d_in[9];
    const float* fc_w = (const float*)d_in[10];
    const float* fc_b = (const float*)d_in[11];
    float* out = (float*)d_out;

    (void)in_sizes; (void)n_in; (void)out_size;

    k_init<<<1184, 256>>>();   // persistent-style grid (148 SMs * 8 blocks), strided memset
    k_gemm1<<<NN / 16, 128>>>(x, W1, as1, ad1);
    k_edgeA1<<<(ET + 255) / 256, 256>>>(ei);
    k_edgeB1<<<(ET + 255) / 256, 256>>>(ei);
    k_edgeC1<<<(ET * 32 + 255) / 256, 256>>>(ei);
    k_fin1_gemm2<<<NN / 16, 128>>>(b1, W2, as2, ad2);
    k_edgeA2<<<(ET + 255) / 256, 256>>>(ei);
    k_edgeB2<<<(ET + 255) / 256, 256>>>(ei);
    k_edgeC2<<<(ET * 32 + 255) / 256, 256>>>(ei);
    k_final<<<(NN * 32 + 255) / 256, 256>>>(b2, fc_w, fc_b, out);
}

// round 3
// speedup vs baseline: 2.0342x; 2.0342x over previous
#include <cuda_runtime.h>
#include <math.h>

#define NN 50000
#define NE 800000
#define ET (NE + NN)
#define FIN 128
#define D1 128      // H*C = 4*32
#define H1 4
#define CH 32
#define SCAN_BS 1024
#define SCAN_NB ((NN + SCAN_BS - 1) / SCAN_BS)   // 49

// ---------------- scratch (device globals; no allocation allowed) -------------
__device__ float g_h1  [NN * D1];
__device__ float g_es1 [NN * H1];
__device__ float g_ed1 [NN * H1];
__device__ float g_out1[NN * D1];
__device__ float g_h2  [NN * CH];
__device__ float g_es2 [NN];
__device__ float g_ed2 [NN];
__device__ float g_out2[NN * CH];
// CSR-by-dst
__device__ int   g_cnt   [NN];
__device__ int   g_offs  [NN + 1];
__device__ int   g_cursor[NN];
__device__ int   g_blk   [64];
__device__ int   g_srcidx[ET];

__device__ __forceinline__ float lrelu(float x) { return x > 0.f ? x : 0.2f * x; }

// ================= CSR build ====================================================
__global__ void k_cinit() {               // self-loop seeds every count with 1
    int i = blockIdx.x * blockDim.x + threadIdx.x;
    if (i < NN) g_cnt[i] = 1;
}

__global__ void k_count(const int* __restrict__ ei) {
    int i = blockIdx.x * blockDim.x + threadIdx.x;
    if (i < NE) atomicAdd(&g_cnt[ei[NE + i]], 1);
}

__global__ void k_scan1() {
    __shared__ int wsum[32];
    const int t = threadIdx.x, b = blockIdx.x;
    const int i = b * SCAN_BS + t;
    const int lane = t & 31, wid = t >> 5;
    int v = (i < NN) ? g_cnt[i] : 0;
    int x = v;
#pragma unroll
    for (int o = 1; o < 32; o <<= 1) {
        int n = __shfl_up_sync(0xFFFFFFFFu, x, o);
        if (lane >= o) x += n;
    }
    if (lane == 31) wsum[wid] = x;
    __syncthreads();
    if (wid == 0) {
        int y = wsum[lane];
#pragma unroll
        for (int o = 1; o < 32; o <<= 1) {
            int n = __shfl_up_sync(0xFFFFFFFFu, y, o);
            if (lane >= o) y += n;
        }
        wsum[lane] = y;
    }
    __syncthreads();
    int excl = x - v + (wid ? wsum[wid - 1] : 0);
    if (i < NN) g_offs[i] = excl;
    if (t == SCAN_BS - 1) g_blk[b] = excl + v;   // block total
}

__global__ void k_scan2() {
    __shared__ int sh[64];
    int t = threadIdx.x;
    sh[t] = (t < SCAN_NB) ? g_blk[t] : 0;
    __syncthreads();
    if (t == 0) {
        int c = 0;
        for (int j = 0; j < SCAN_NB; j++) { int v = sh[j]; sh[j] = c; c += v; }
    }
    __syncthreads();
    if (t < SCAN_NB) g_blk[t] = sh[t];
}

__global__ void k_scan3() {
    int i = blockIdx.x * blockDim.x + threadIdx.x;
    if (i < NN) {
        int off = g_offs[i] + g_blk[i >> 10];
        g_offs[i] = off;
        g_cursor[i] = off;
    }
    if (i == 0) g_offs[NN] = ET;
}

__global__ void k_scatter(const int* __restrict__ ei) {
    int i = blockIdx.x * blockDim.x + threadIdx.x;
    if (i >= ET) return;
    int s, d;
    if (i < NE) { s = ei[i]; d = ei[NE + i]; } else { s = d = i - NE; }
    int pos = atomicAdd(&g_cursor[d], 1);
    g_srcidx[pos] = s;
}

// ================= layer1 GEMM + attention logits ===============================
__global__ void k_gemm1(const float* __restrict__ x, const float* __restrict__ W1,
                        const float* __restrict__ as1, const float* __restrict__ ad1) {
    __shared__ float xs[16][FIN];
    const int t = threadIdx.x;
    const int nb = blockIdx.x * 16;
#pragma unroll
    for (int r = 0; r < 16; r++) xs[r][t] = x[(nb + r) * FIN + t];
    __syncthreads();

    float acc[16];
#pragma unroll
    for (int r = 0; r < 16; r++) acc[r] = 0.f;
    for (int k = 0; k < FIN; k++) {
        float w = W1[k * D1 + t];
#pragma unroll
        for (int r = 0; r < 16; r++) acc[r] += xs[r][k] * w;
    }

    const float a_s = as1[t], a_d = ad1[t];
    const int lane = t & 31, head = t >> 5;
#pragma unroll
    for (int r = 0; r < 16; r++) {
        int n = nb + r;
        g_h1[n * D1 + t] = acc[r];
        float s = acc[r] * a_s;
        float d = acc[r] * a_d;
#pragma unroll
        for (int o = 16; o; o >>= 1) {
            s += __shfl_xor_sync(0xFFFFFFFFu, s, o);
            d += __shfl_xor_sync(0xFFFFFFFFu, d, o);
        }
        if (lane == 0) { g_es1[n * H1 + head] = s; g_ed1[n * H1 + head] = d; }
    }
}

// ================= layer1 aggregation: one warp per dst =========================
__global__ void k_agg1() {
    const int gw = (blockIdx.x * blockDim.x + threadIdx.x) >> 5;   // dst node
    const int lane = threadIdx.x & 31;
    const int wi = threadIdx.x >> 5;
    __shared__ float wb[8][32][4];
    __shared__ int   sb[8][32];
    if (gw >= NN) return;

    const int beg = g_offs[gw], end = g_offs[gw + 1];
    const float4 ed = *(const float4*)(g_ed1 + gw * 4);
    float acc0 = 0.f, acc1 = 0.f, acc2 = 0.f, acc3 = 0.f;
    float den0 = 0.f, den1 = 0.f, den2 = 0.f, den3 = 0.f;

    for (int base = beg; base < end; base += 32) {
        const int cnt = min(32, end - base);
        if (lane < cnt) {
            int s = g_srcidx[base + lane];
            float4 es = *(const float4*)(g_es1 + s * 4);
            float4 wv;
            wv.x = __expf(lrelu(es.x + ed.x));
            wv.y = __expf(lrelu(es.y + ed.y));
            wv.z = __expf(lrelu(es.z + ed.z));
            wv.w = __expf(lrelu(es.w + ed.w));
            den0 += wv.x; den1 += wv.y; den2 += wv.z; den3 += wv.w;
            sb[wi][lane] = s;
            *(float4*)&wb[wi][lane][0] = wv;
        }
        __syncwarp();
        for (int j = 0; j < cnt; j++) {
            const float* hs = g_h1 + (size_t)sb[wi][j] * D1;
            float4 wj = *(const float4*)&wb[wi][j][0];
            acc0 += hs[lane]      * wj.x;
            acc1 += hs[32 + lane] * wj.y;
            acc2 += hs[64 + lane] * wj.z;
            acc3 += hs[96 + lane] * wj.w;
        }
        __syncwarp();
    }
#pragma unroll
    for (int o = 16; o; o >>= 1) {
        den0 += __shfl_xor_sync(0xFFFFFFFFu, den0, o);
        den1 += __shfl_xor_sync(0xFFFFFFFFu, den1, o);
        den2 += __shfl_xor_sync(0xFFFFFFFFu, den2, o);
        den3 += __shfl_xor_sync(0xFFFFFFFFu, den3, o);
    }
    float* od = g_out1 + (size_t)gw * D1;
    od[lane]      = acc0 / (den0 + 1e-16f);
    od[32 + lane] = acc1 / (den1 + 1e-16f);
    od[64 + lane] = acc2 / (den2 + 1e-16f);
    od[96 + lane] = acc3 / (den3 + 1e-16f);
}

// ================= finalize layer1 (+b1, relu), GEMM2, attention logits =========
__global__ void k_fin1_gemm2(const float* __restrict__ b1, const float* __restrict__ W2,
                             const float* __restrict__ as2, const float* __restrict__ ad2) {
    __shared__ float xs[16][D1];
    __shared__ float sh2[16][CH + 1];
    const int t = threadIdx.x;
    const int nb = blockIdx.x * 16;
    const float bt = b1[t];
#pragma unroll
    for (int r = 0; r < 16; r++)
        xs[r][t] = fmaxf(g_out1[(size_t)(nb + r) * D1 + t] + bt, 0.f);
    __syncthreads();

    const int c = t & 31, rg = t >> 5;
    float acc[4] = {0.f, 0.f, 0.f, 0.f};
    for (int k = 0; k < D1; k++) {
        float w = W2[k * CH + c];
        acc[0] += xs[rg     ][k] * w;
        acc[1] += xs[rg + 4 ][k] * w;
        acc[2] += xs[rg + 8 ][k] * w;
        acc[3] += xs[rg + 12][k] * w;
    }
#pragma unroll
    for (int i = 0; i < 4; i++) {
        int r = rg + 4 * i;
        g_h2[(size_t)(nb + r) * CH + c] = acc[i];
        sh2[r][c] = acc[i];
    }
    __syncthreads();

    const float as2c = as2[c], ad2c = ad2[c];
#pragma unroll
    for (int i = 0; i < 4; i++) {
        int r = rg + 4 * i;
        float s = sh2[r][c] * as2c;
        float d = sh2[r][c] * ad2c;
#pragma unroll
        for (int o = 16; o; o >>= 1) {
            s += __shfl_xor_sync(0xFFFFFFFFu, s, o);
            d += __shfl_xor_sync(0xFFFFFFFFu, d, o);
        }
        if (c == 0) { g_es2[nb + r] = s; g_ed2[nb + r] = d; }
    }
}

// ================= layer2 aggregation: one warp per dst =========================
__global__ void k_agg2() {
    const int gw = (blockIdx.x * blockDim.x + threadIdx.x) >> 5;
    const int lane = threadIdx.x & 31;
    const int wi = threadIdx.x >> 5;
    __shared__ float wb[8][32];
    __shared__ int   sb[8][32];
    if (gw >= NN) return;

    const int beg = g_offs[gw], end = g_offs[gw + 1];
    const float edv = g_ed2[gw];
    float acc = 0.f, den = 0.f;

    for (int base = beg; base < end; base += 32) {
        const int cnt = min(32, end - base);
        if (lane < cnt) {
            int s = g_srcidx[base + lane];
            float wv = __expf(lrelu(g_es2[s] + edv));
            den += wv;
            sb[wi][lane] = s;
            wb[wi][lane] = wv;
        }
        __syncwarp();
        for (int j = 0; j < cnt; j++)
            acc += g_h2[(size_t)sb[wi][j] * CH + lane] * wb[wi][j];
        __syncwarp();
    }
#pragma unroll
    for (int o = 16; o; o >>= 1)
        den += __shfl_xor_sync(0xFFFFFFFFu, den, o);
    g_out2[(size_t)gw * CH + lane] = acc / (den + 1e-16f);
}

// ================= final: +b2, relu, FC, sigmoid ================================
__global__ void k_final(const float* __restrict__ b2, const float* __restrict__ fc_w,
                        const float* __restrict__ fc_b, float* __restrict__ out) {
    int n = (blockIdx.x * blockDim.x + threadIdx.x) >> 5;
    int lane = threadIdx.x & 31;
    if (n >= NN) return;
    float v = fmaxf(g_out2[(size_t)n * CH + lane] + b2[lane], 0.f);
    float p = v * fc_w[lane];
#pragma unroll
    for (int o = 16; o; o >>= 1) p += __shfl_xor_sync(0xFFFFFFFFu, p, o);
    if (lane == 0) out[n] = 1.f / (1.f + expf(-(p + fc_b[0])));
}

// ================= launch =======================================================
extern "C" void kernel_launch(void* const* d_in, const int* in_sizes, int n_in,
                              void* d_out, int out_size) {
    const float* x    = (const float*)d_in[0];
    const int*   ei   = (const int*)  d_in[1];
    const float* W1   = (const float*)d_in[2];
    const float* as1  = (const float*)d_in[3];
    const float* ad1  = (const float*)d_in[4];
    const float* b1   = (const float*)d_in[5];
    const float* W2   = (const float*)d_in[6];
    const float* as2  = (const float*)d_in[7];
    const float* ad2  = (const float*)d_in[8];
    const float* b2   = (const float*)d_in[9];
    const float* fc_w = (const float*)d_in[10];
    const float* fc_b = (const float*)d_in[11];
    float* out = (float*)d_out;
    (void)in_sizes; (void)n_in; (void)out_size;

    // CSR build (dst-sorted adjacency; shared by both layers)
    k_cinit  <<<(NN + 255) / 256, 256>>>();
    k_count  <<<(NE + 255) / 256, 256>>>(ei);
    k_scan1  <<<SCAN_NB, SCAN_BS>>>();
    k_scan2  <<<1, 64>>>();
    k_scan3  <<<(NN + 255) / 256, 256>>>();
    k_scatter<<<(ET + 255) / 256, 256>>>(ei);

    // Layer 1
    k_gemm1<<<NN / 16, 128>>>(x, W1, as1, ad1);
    k_agg1 <<<(NN * 32 + 255) / 256, 256>>>();

    // Layer 2
    k_fin1_gemm2<<<NN / 16, 128>>>(b1, W2, as2, ad2);
    k_agg2      <<<(NN * 32 + 255) / 256, 256>>>();

    // Head
    k_final<<<(NN * 32 + 255) / 256, 256>>>(b2, fc_w, fc_b, out);
}